// round 16
// baseline (speedup 1.0000x reference)
#include <cuda_runtime.h>
#include <cstdint>

// Screen / tiling constants (W=1280, H=720 are exact multiples of L=16)
#define W_SCREEN 1280.0f
#define H_SCREEN 720.0f
#define NBW      80
#define NBH      45
#define N_POINTS 32768
#define ROWS_PER_CTA 5     // 45 = 9 * 5  (was 9x5; now finer bands)
#define BANDS    9

// R15 champion structure, one change: finer row bands (5 rows/CTA, 9 bands)
// to shrink the sub-saturated tail wave (46080 CTAs = 19.46 waves; tail
// bytes 35 MB -> 19 MB).
// One block per (512-point chunk, xi column, 5-row band). Each thread owns 4
// consecutive points, computes their AABB -> tile-row interval [a, a+n) in
// the prolog (n = 0 when this xi column misses the point's x-interval), then
// sweeps its 5 rows emitting one float4 (STG.128, evict-first) per row.
//
// Reference condition per (tile, point):
//   min(xmax,right) > max(xmin,left) && min(ymax,bottom) > max(ymin,top)
// With right=left+16, bottom=top+16 exact (W,H multiples of 16) and
// xmax>xmin, ymax>ymin guaranteed (radius >= 1), this reduces to the
// separable interval test; the y part becomes (unsigned)(yi - a) < n.
__global__ __launch_bounds__(128) void fused_mask_kernel(
        const float* __restrict__ pos2d,
        const float* __restrict__ radius,
        float* __restrict__ out) {
    int g  = blockIdx.x * 128 + threadIdx.x;   // 4-point group, 0..8191
    int xi = blockIdx.y;                       // 0..79
    int y0 = blockIdx.z * ROWS_PER_CTA;        // 0, 5, 10, ..., 40
    int left  = xi * 16;
    int right = left + 16;

    // Load this thread's 4 points (48 bytes, fully coalesced; L2-resident).
    float4 q01 = reinterpret_cast<const float4*>(pos2d)[2 * g];      // pts 4g,4g+1
    float4 q23 = reinterpret_cast<const float4*>(pos2d)[2 * g + 1];  // pts 4g+2,4g+3
    float4 r4  = reinterpret_cast<const float4*>(radius)[g];

    unsigned a[4], n[4];
    {
        float xs[4] = {q01.x, q01.z, q23.x, q23.z};
        float ys[4] = {q01.y, q01.w, q23.y, q23.w};
        float rs[4] = {r4.x, r4.y, r4.z, r4.w};
#pragma unroll
        for (int j = 0; j < 4; j++) {
            float x = xs[j], y = ys[j], r = rs[j];
            int xmin = (int)fminf(fmaxf(x - r, 0.0f), W_SCREEN);
            int xmax = (int)fminf(fmaxf(x + r, 0.0f), W_SCREEN);
            int ymin = (int)fminf(fmaxf(y - r, 0.0f), H_SCREEN);
            int ymax = (int)fminf(fmaxf(y + r, 0.0f), H_SCREEN);

            bool okx = (xmax > left) && (xmin < right);
            unsigned aj = (unsigned)(ymin >> 4);               // first valid yi
            unsigned bj = (unsigned)(((ymax - 1) >> 4) + 1);   // one past last
            a[j] = aj;
            n[j] = okx ? (bj - aj) : 0u;                       // interval length
        }
    }

    float* optr = out + ((size_t)xi * NBH + y0) * N_POINTS + (size_t)g * 4;

#pragma unroll
    for (int k = 0; k < ROWS_PER_CTA; k++) {
        int yi = y0 + k;
        float4 v;
        v.x = ((unsigned)(yi - a[0]) < n[0]) ? 1.0f : 0.0f;
        v.y = ((unsigned)(yi - a[1]) < n[1]) ? 1.0f : 0.0f;
        v.z = ((unsigned)(yi - a[2]) < n[2]) ? 1.0f : 0.0f;
        v.w = ((unsigned)(yi - a[3]) < n[3]) ? 1.0f : 0.0f;
        __stcs(reinterpret_cast<float4*>(optr), v);   // streaming, zero reuse
        optr += N_POINTS;
    }
}

extern "C" void kernel_launch(void* const* d_in, const int* in_sizes, int n_in,
                              void* d_out, int out_size) {
    const float* pos2d  = (const float*)d_in[0];   // [32768, 2] float32
    const float* radius = (const float*)d_in[1];   // [32768]    float32
    float* out          = (float*)d_out;           // [3600, 32768] float32

    dim3 grid(64, NBW, BANDS);                     // 64 chunks x 80 xi x 9 bands
    fused_mask_kernel<<<grid, 128>>>(pos2d, radius, out);
}

// round 17
// speedup vs baseline: 1.0033x; 1.0033x over previous
#include <cuda_runtime.h>
#include <cstdint>

// Screen / tiling constants (W=1280, H=720 are exact multiples of L=16)
#define W_SCREEN 1280.0f
#define H_SCREEN 720.0f
#define NBW      80
#define NBH      45
#define N_POINTS 32768
#define ROWS_PER_CTA 9     // optimum from the R4/R15/R16 band-size sweep
#define BANDS    5

// R15 champion structure, one change: float-domain x-test in the prolog.
// For integer left/right, monotone trunc/clamp give exactly:
//   xmax > left  <=>  x + r >= left + 1
//   xmin < right <=>  x - r <  right
// so the x side needs no clamp/convert at all (2 FADD + 2 FSETP per point).
//
// One block per (512-point chunk, xi column, 9-row band). Each thread owns 4
// consecutive points, computes the y tile-row interval [a, a+n) (n forced to
// 0 when this xi column misses the point's x-interval), then sweeps its 9
// rows emitting one float4 (STG.128, evict-first streaming) per row.
//
// Reference condition per (tile, point):
//   min(xmax,right) > max(xmin,left) && min(ymax,bottom) > max(ymin,top)
// With right=left+16, bottom=top+16 exact (W,H multiples of 16) and
// xmax>xmin, ymax>ymin guaranteed (radius >= 1), this reduces to the
// separable interval test; the y part becomes (unsigned)(yi - a) < n.
__global__ __launch_bounds__(128) void fused_mask_kernel(
        const float* __restrict__ pos2d,
        const float* __restrict__ radius,
        float* __restrict__ out) {
    int g  = blockIdx.x * 128 + threadIdx.x;   // 4-point group, 0..8191
    int xi = blockIdx.y;                       // 0..79
    int y0 = blockIdx.z * ROWS_PER_CTA;        // 0, 9, 18, 27, 36
    float leftp1 = (float)(xi * 16 + 1);       // left + 1
    float rightf = (float)(xi * 16 + 16);      // right

    // Load this thread's 4 points (48 bytes, fully coalesced; L2-resident).
    float4 q01 = reinterpret_cast<const float4*>(pos2d)[2 * g];      // pts 4g,4g+1
    float4 q23 = reinterpret_cast<const float4*>(pos2d)[2 * g + 1];  // pts 4g+2,4g+3
    float4 r4  = reinterpret_cast<const float4*>(radius)[g];

    unsigned a[4], n[4];
    {
        float xs[4] = {q01.x, q01.z, q23.x, q23.z};
        float ys[4] = {q01.y, q01.w, q23.y, q23.w};
        float rs[4] = {r4.x, r4.y, r4.z, r4.w};
#pragma unroll
        for (int j = 0; j < 4; j++) {
            float x = xs[j], y = ys[j], r = rs[j];

            // x-test entirely in float (see header proof).
            bool okx = (x + r >= leftp1) && (x - r < rightf);

            // y tile-row interval (integer domain, as in reference).
            int ymin = (int)fminf(fmaxf(y - r, 0.0f), H_SCREEN);
            int ymax = (int)fminf(fmaxf(y + r, 0.0f), H_SCREEN);
            unsigned aj = (unsigned)(ymin >> 4);               // first valid yi
            unsigned bj = (unsigned)(((ymax - 1) >> 4) + 1);   // one past last
            a[j] = aj;
            n[j] = okx ? (bj - aj) : 0u;                       // interval length
        }
    }

    float* optr = out + ((size_t)xi * NBH + y0) * N_POINTS + (size_t)g * 4;

#pragma unroll
    for (int k = 0; k < ROWS_PER_CTA; k++) {
        int yi = y0 + k;
        float4 v;
        v.x = ((unsigned)(yi - a[0]) < n[0]) ? 1.0f : 0.0f;
        v.y = ((unsigned)(yi - a[1]) < n[1]) ? 1.0f : 0.0f;
        v.z = ((unsigned)(yi - a[2]) < n[2]) ? 1.0f : 0.0f;
        v.w = ((unsigned)(yi - a[3]) < n[3]) ? 1.0f : 0.0f;
        __stcs(reinterpret_cast<float4*>(optr), v);   // streaming, zero reuse
        optr += N_POINTS;
    }
}

extern "C" void kernel_launch(void* const* d_in, const int* in_sizes, int n_in,
                              void* d_out, int out_size) {
    const float* pos2d  = (const float*)d_in[0];   // [32768, 2] float32
    const float* radius = (const float*)d_in[1];   // [32768]    float32
    float* out          = (float*)d_out;           // [3600, 32768] float32

    dim3 grid(64, NBW, BANDS);                     // 64 chunks x 80 xi x 5 bands
    fused_mask_kernel<<<grid, 128>>>(pos2d, radius, out);
}